// round 15
// baseline (speedup 1.0000x reference)
#include <cuda_runtime.h>
#include <cuda_bf16.h>

#define R_TOTAL 65536   // T*B = 2048*32
#define XDIM    1024

// ---- scratch (static device arrays; no allocation) ----
__device__ float g_h2[(size_t)R_TOTAL * 128];   // [row][mlp(2)][64]   32 MB
__device__ float g_part[8][R_TOTAL];            // per-colblock partial row sums (log2-domain)

__device__ __forceinline__ float ex2f(float x){ float r; asm("ex2.approx.f32 %0, %1;" : "=f"(r) : "f"(x)); return r; }
__device__ __forceinline__ float lg2f(float x){ float r; asm("lg2.approx.f32 %0, %1;" : "=f"(r) : "f"(x)); return r; }

__device__ __forceinline__ float tanh_fast(float x){
    float xc = fminf(fmaxf(x, -9.0f), 9.0f);
    float e  = ex2f(xc * 2.885390081777927f);   // e^{2x}
    return __fdividef(e - 1.0f, e + 1.0f);
}

// ---- packed f32x2 helpers ----
typedef unsigned long long ull;
__device__ __forceinline__ void ffma2(ull &d, ull a, ull b){
    asm("fma.rn.f32x2 %0, %1, %2, %0;" : "+l"(d) : "l"(a), "l"(b));
}
__device__ __forceinline__ ull mul2(ull a, ull b){
    ull d; asm("mul.rn.f32x2 %0, %1, %2;" : "=l"(d) : "l"(a), "l"(b)); return d;
}
__device__ __forceinline__ ull add2(ull a, ull b){
    ull d; asm("add.rn.f32x2 %0, %1, %2;" : "=l"(d) : "l"(a), "l"(b)); return d;
}
__device__ __forceinline__ ull pk2(float lo, float hi){
    ull d; asm("mov.b64 %0, {%1, %2};" : "=l"(d) : "f"(lo), "f"(hi)); return d;
}
__device__ __forceinline__ void upk2(float &lo, float &hi, ull u){
    asm("mov.b64 {%0, %1}, %2;" : "=f"(lo), "=f"(hi) : "l"(u));
}
__device__ __forceinline__ ull dup2(float f){
    ull d; asm("mov.b64 %0, {%1, %1};" : "=l"(d) : "f"(f)); return d;
}
__device__ __forceinline__ ull pack_dup(float f){
    unsigned int b = __float_as_uint(f);
    return ((ull)b << 32) | (ull)b;
}
__device__ __forceinline__ ull pack2i(float f0, float f1){
    return ((ull)__float_as_uint(f1) << 32) | (ull)__float_as_uint(f0);
}
__device__ __forceinline__ ull ex2_2(ull g){
    float l, h; upk2(l, h, g);
    return pk2(ex2f(l), ex2f(h));
}

// ===========================================================================
// K1: layers 1+2 for both MLPs. 64 rows per block, 256 threads. (R12 form)
// ===========================================================================
#define K1_XSH   0
#define K1_H1T   (64*32)
#define K1_W2SH  (K1_H1T + 2*256*68)
#define K1_SMEM_FLOATS (K1_W2SH + 2*64*64)

__global__ void __launch_bounds__(256, 1) k1_mlp12(
    const float* __restrict__ w,
    const float* __restrict__ W1r, const float* __restrict__ b1r,
    const float* __restrict__ W2r, const float* __restrict__ b2r,
    const float* __restrict__ W1v, const float* __restrict__ b1v,
    const float* __restrict__ W2v, const float* __restrict__ b2v)
{
    extern __shared__ float sm[];
    float* xsh  = sm + K1_XSH;
    float* h1t  = sm + K1_H1T;     // [m][k][r] stride 68
    float* w2sh = sm + K1_W2SH;

    const int tid  = threadIdx.x;
    const int row0 = blockIdx.x * 64;

    {
        const float4* src = (const float4*)(w + (size_t)row0 * 32);
        float4* dst = (float4*)xsh;
        for (int i = tid; i < 64*32/4; i += 256) dst[i] = src[i];
    }

    const int c = tid;
    float w1a[16], w1b[16];
    #pragma unroll
    for (int k = 0; k < 16; k++){ w1a[k] = W1r[k*256 + c]; w1b[k] = W1v[k*256 + c]; }
    const float ba = b1r[c], bb = b1v[c];
    __syncthreads();

    #pragma unroll 2
    for (int r2 = 0; r2 < 64; r2 += 2){
        float h0p[2], h1p[2];
        #pragma unroll
        for (int u = 0; u < 2; u++){
            const int r = r2 + u;
            float xr[32];
            #pragma unroll
            for (int q = 0; q < 8; q++) *(float4*)&xr[q*4] = *(float4*)&xsh[r*32 + q*4];
            float a0 = ba, a1 = bb;
            #pragma unroll
            for (int k = 0; k < 8; k++){
                a0 = fmaf(xr[k],      w1a[k],     a0);
                a0 = fmaf(xr[k + 16], w1a[k + 8], a0);
                a1 = fmaf(xr[k + 8],  w1b[k],     a1);
                a1 = fmaf(xr[k + 24], w1b[k + 8], a1);
            }
            h0p[u] = tanh_fast(a0);
            h1p[u] = tanh_fast(a1);
        }
        *(ull*)&h1t[(0*256 + c)*68 + r2] = pack2i(h0p[0], h0p[1]);
        *(ull*)&h1t[(1*256 + c)*68 + r2] = pack2i(h1p[0], h1p[1]);
    }

    const int ci = tid & 15, rg = tid >> 4;
    const int c0 = ci * 4,  r0 = rg * 4;

    ull acc[2][2][4];
    {
        float4 br = *(const float4*)&b2r[c0];
        float4 bv = *(const float4*)&b2v[c0];
        #pragma unroll
        for (int rp = 0; rp < 2; rp++){
            acc[0][rp][0] = pack_dup(br.x); acc[0][rp][1] = pack_dup(br.y);
            acc[0][rp][2] = pack_dup(br.z); acc[0][rp][3] = pack_dup(br.w);
            acc[1][rp][0] = pack_dup(bv.x); acc[1][rp][1] = pack_dup(bv.y);
            acc[1][rp][2] = pack_dup(bv.z); acc[1][rp][3] = pack_dup(bv.w);
        }
    }

    for (int kc = 0; kc < 4; kc++){
        __syncthreads();
        for (int q = tid; q < 2048; q += 256){
            int m   = q >> 10;
            int rem = q & 1023;
            int kk  = rem >> 4;
            int cq  = rem & 15;
            const float* W2m = m ? W2v : W2r;
            *(float4*)&w2sh[(m*64 + kk)*64 + cq*4] =
                *(const float4*)&W2m[(kc*64 + kk)*64 + cq*4];
        }
        __syncthreads();
        #pragma unroll 4
        for (int kk = 0; kk < 64; kk++){
            const int k = kc*64 + kk;
            float4 wr = *(float4*)&w2sh[(0*64 + kk)*64 + c0];
            float4 wv = *(float4*)&w2sh[(1*64 + kk)*64 + c0];
            ulonglong2 hA = *(const ulonglong2*)&h1t[(0*256 + k)*68 + r0];
            ulonglong2 hB = *(const ulonglong2*)&h1t[(1*256 + k)*68 + r0];
            ull wd;
            wd = dup2(wr.x); ffma2(acc[0][0][0], hA.x, wd); ffma2(acc[0][1][0], hA.y, wd);
            wd = dup2(wr.y); ffma2(acc[0][0][1], hA.x, wd); ffma2(acc[0][1][1], hA.y, wd);
            wd = dup2(wr.z); ffma2(acc[0][0][2], hA.x, wd); ffma2(acc[0][1][2], hA.y, wd);
            wd = dup2(wr.w); ffma2(acc[0][0][3], hA.x, wd); ffma2(acc[0][1][3], hA.y, wd);
            wd = dup2(wv.x); ffma2(acc[1][0][0], hB.x, wd); ffma2(acc[1][1][0], hB.y, wd);
            wd = dup2(wv.y); ffma2(acc[1][0][1], hB.x, wd); ffma2(acc[1][1][1], hB.y, wd);
            wd = dup2(wv.z); ffma2(acc[1][0][2], hB.x, wd); ffma2(acc[1][1][2], hB.y, wd);
            wd = dup2(wv.w); ffma2(acc[1][0][3], hB.x, wd); ffma2(acc[1][1][3], hB.y, wd);
        }
    }

    #pragma unroll
    for (int m = 0; m < 2; m++){
        #pragma unroll
        for (int rp = 0; rp < 2; rp++){
            float lo0, hi0, lo1, hi1, lo2, hi2, lo3, hi3;
            upk2(lo0, hi0, acc[m][rp][0]);
            upk2(lo1, hi1, acc[m][rp][1]);
            upk2(lo2, hi2, acc[m][rp][2]);
            upk2(lo3, hi3, acc[m][rp][3]);
            float4 oLo, oHi;
            oLo.x = tanh_fast(lo0); oLo.y = tanh_fast(lo1);
            oLo.z = tanh_fast(lo2); oLo.w = tanh_fast(lo3);
            oHi.x = tanh_fast(hi0); oHi.y = tanh_fast(hi1);
            oHi.z = tanh_fast(hi2); oHi.w = tanh_fast(hi3);
            const int rowLo = row0 + r0 + rp*2;
            *(float4*)&g_h2[((size_t)rowLo*2 + m)*64 + c0]     = oLo;
            *(float4*)&g_h2[((size_t)(rowLo+1)*2 + m)*64 + c0] = oHi;
        }
    }
}

// ===========================================================================
// K2: warp-specialized producer/consumer pipeline.
// 256 threads: warps 0-3 GEMM producers, warps 4-7 elementwise consumers.
// grid (2048, 2); each CTA: rowblock bx (32 rows) x 4 col-tiles (128 cols each).
// Double-buffered y in smem; one __syncthreads per phase.
// smem: h2p 32KB | w3sh 32KB | y[2] 64KB | lut  -> ~128KB, 1 CTA/SM.
// ===========================================================================
#define K2_OFF_W3   (32*128*8)                 // 32768
#define K2_OFF_Y    (K2_OFF_W3 + 2*32*128*4)   // 65536
#define K2_OFF_LUT  (K2_OFF_Y + 2*2*32*64*8)   // 131072
#define K2_SMEM_BYTES (K2_OFF_LUT + 64)        // 131136

__global__ void __launch_bounds__(256, 1) k2_layer3(
    const float* __restrict__ data,
    const float* __restrict__ W3r, const float* __restrict__ b3r,
    const float* __restrict__ W3v, const float* __restrict__ b3v)
{
    extern __shared__ __align__(16) char smraw[];
    ull*   h2p  = (ull*)smraw;                       // 4096 ull
    float* w3sh = (float*)(smraw + K2_OFF_W3);       // 8192 floats ([m][kk<32][128])
    ull*   ysm  = (ull*)(smraw + K2_OFF_Y);          // [buf][m][row(32)][colpair(64)]
    float* lut  = (float*)(smraw + K2_OFF_LUT);

    const int tid  = threadIdx.x;
    const int row0 = blockIdx.x * 32;
    const int wid  = tid >> 5;
    const int lane = tid & 31;

    if (tid < 10){
        const float LGF[10] = {
            0.0f, 0.0f, 0.6931471805599453f, 1.791759469228055f, 3.1780538303479458f,
            4.787491742782046f, 6.579251212010101f, 8.525161361065415f,
            10.604602902745251f, 12.801827480081469f };
        lut[tid] = LGF[tid];
    }
    // stage h2 as duplicated (h,h) pairs
    for (int q = tid; q < 4096; q += 256){
        int rr  = q >> 7;
        int rem = q & 127;
        h2p[rr*128 + rem] = pack_dup(g_h2[(size_t)(row0 + rr)*128 + rem]);
    }
    __syncthreads();

    // elementwise constants
    const float LOG2E = 1.4426950408889634f;
    const float C_NLG2LN2 = 0.5287663729448977f;
    const ull   ONE2 = 0x3F8000003F800000ULL;
    const float LN10F = 15.104412573075516f;
    const ull CN2  = pack_dup(-0.6931471805599453f);
    const ull CN3  = pack_dup(-1.0986122886681098f);
    const ull CN5  = pack_dup(-1.6094379124341003f);
    const ull CN7  = pack_dup(-1.9459101090932196f);
    const ull CN11 = pack_dup(-2.3978952727983707f);
    const ull CN13 = pack_dup(-2.5649493574615367f);
    const ull CN17 = pack_dup(-2.833213344056216f);
    const ull CN19 = pack_dup(-2.9444389791664403f);

    const ulonglong2* w3u = (const ulonglong2*)w3sh;
    const float4* s0 = (const float4*)W3r;
    const float4* s1 = (const float4*)W3v;
    const float4* br4 = (const float4*)b3r;
    const float4* bv4 = (const float4*)b3v;

    for (int ph = 0; ph < 5; ph++){
        if (wid < 4 && ph < 4){
            // ================= PRODUCER: GEMM tile ph =================
            const int cb  = blockIdx.y*4 + ph;
            const int buf = ph & 1;
            const int pwid = wid;

            ull acc[2][8][2];
            {
                float4 br = br4[cb*32 + lane];
                float4 bv = bv4[cb*32 + lane];
                #pragma unroll
                for (int rr = 0; rr < 8; rr++){
                    acc[0][rr][0] = pack2i(br.x, br.y);
                    acc[0][rr][1] = pack2i(br.z, br.w);
                    acc[1][rr][0] = pack2i(bv.x, bv.y);
                    acc[1][rr][1] = pack2i(bv.z, bv.w);
                }
            }

            const ull* h2row = h2p + pwid*8*128;
            #pragma unroll
            for (int kh = 0; kh < 2; kh++){
                // stage w3 half (producers only)
                {
                    float4* dst = (float4*)w3sh;
                    for (int q = tid; q < 2048; q += 128){
                        int m  = q >> 10;
                        int kk = (q >> 5) & 31;
                        int cf = q & 31;
                        dst[q] = (m ? s1 : s0)[(kh*32 + kk)*256 + cb*32 + cf];
                    }
                }
                asm volatile("bar.sync 1, 128;" ::: "memory");

                #pragma unroll 4
                for (int k = 0; k < 32; k += 2){
                    ulonglong2 wr0 = w3u[(size_t)k*32 + lane];
                    ulonglong2 wr1 = w3u[(size_t)(k+1)*32 + lane];
                    ulonglong2 wv0 = w3u[(size_t)(32 + k)*32 + lane];
                    ulonglong2 wv1 = w3u[(size_t)(32 + k + 1)*32 + lane];
                    const int kg = kh*32 + k;
                    #pragma unroll
                    for (int rr = 0; rr < 8; rr++){
                        ulonglong2 h0p = *(const ulonglong2*)&h2row[rr*128 + kg];
                        ulonglong2 h1p = *(const ulonglong2*)&h2row[rr*128 + 64 + kg];
                        ffma2(acc[0][rr][0], h0p.x, wr0.x);
                        ffma2(acc[0][rr][1], h0p.x, wr0.y);
                        ffma2(acc[0][rr][0], h0p.y, wr1.x);
                        ffma2(acc[0][rr][1], h0p.y, wr1.y);
                        ffma2(acc[1][rr][0], h1p.x, wv0.x);
                        ffma2(acc[1][rr][1], h1p.x, wv0.y);
                        ffma2(acc[1][rr][0], h1p.y, wv1.x);
                        ffma2(acc[1][rr][1], h1p.y, wv1.y);
                    }
                }
                asm volatile("bar.sync 1, 128;" ::: "memory");   // protect w3sh reuse
            }

            // write y[buf]
            #pragma unroll
            for (int m = 0; m < 2; m++){
                #pragma unroll
                for (int rr = 0; rr < 8; rr++){
                    ulonglong2 st; st.x = acc[m][rr][0]; st.y = acc[m][rr][1];
                    *(ulonglong2*)&ysm[((size_t)(buf*2 + m)*32 + pwid*8 + rr)*64 + lane*2] = st;
                }
            }
        }
        else if (wid >= 4 && ph >= 1){
            // ================= CONSUMER: elementwise tile ph-1 =================
            const int tc   = ph - 1;
            const int cbc  = blockIdx.y*4 + tc;
            const int buf  = tc & 1;
            const int cwid = wid - 4;

            // prefetch data rows
            float4 d4a[8];
            #pragma unroll
            for (int rr = 0; rr < 8; rr++)
                d4a[rr] = *(const float4*)&data[(size_t)(row0 + cwid*8 + rr)*1024 + cbc*128 + lane*4];

            float srow[8];
            #pragma unroll
            for (int rr = 0; rr < 8; rr++) srow[rr] = 0.0f;

            #pragma unroll
            for (int rr = 0; rr < 8; rr++){
                ulonglong2 yA = *(const ulonglong2*)&ysm[((size_t)(buf*2 + 0)*32 + cwid*8 + rr)*64 + lane*2];
                ulonglong2 yB = *(const ulonglong2*)&ysm[((size_t)(buf*2 + 1)*32 + cwid*8 + rr)*64 + lane*2];
                float dvp[2][2] = {{d4a[rr].x, d4a[rr].y}, {d4a[rr].z, d4a[rr].w}};

                #pragma unroll
                for (int p = 0; p < 2; p++){
                    float ya0, ya1, yb0, yb1;
                    upk2(ya0, ya1, p ? yA.y : yA.x);
                    upk2(yb0, yb1, p ? yB.y : yB.x);

                    float lr2h[2], sbh[2], rateh[2];
                    #pragma unroll
                    for (int h = 0; h < 2; h++){
                        float ya = h ? ya1 : ya0;
                        float yb = h ? yb1 : yb0;
                        float ta  = ya * LOG2E;
                        float spa = fmaxf(ta, 0.0f) + lg2f(1.0f + ex2f(-fabsf(ta)));
                        lr2h[h]   = C_NLG2LN2 - lg2f(spa);
                        float tb  = yb * LOG2E;
                        sbh[h]    = fmaxf(tb, 0.0f) + lg2f(1.0f + ex2f(-fabsf(tb)));
                        rateh[h]  = ex2f(lr2h[h]);
                    }

                    ull sb2 = pk2(sbh[0], sbh[1]);
                    ull A2  = ex2_2(mul2(sb2, CN2));
                    ull A3  = ex2_2(mul2(sb2, CN3));
                    ull A5  = ex2_2(mul2(sb2, CN5));
                    ull A7  = ex2_2(mul2(sb2, CN7));
                    ull A11 = ex2_2(mul2(sb2, CN11));
                    ull A13 = ex2_2(mul2(sb2, CN13));
                    ull A17 = ex2_2(mul2(sb2, CN17));
                    ull A19 = ex2_2(mul2(sb2, CN19));

                    ull R = pk2(rateh[0], rateh[1]);

                    ull B2 = mul2(R, A2);
                    ull B3 = mul2(R, A3);
                    ull B4 = mul2(B2, A2);
                    ull B8 = mul2(B4, A2);
                    ull B9 = mul2(B3, A3);

                    ull tA = R;
                    ull ZA = add2(ONE2, tA);
                    tA = mul2(tA, B2);            ZA = add2(ZA, tA);
                    tA = mul2(tA, B3);            ZA = add2(ZA, tA);
                    tA = mul2(tA, B4);            ZA = add2(ZA, tA);
                    tA = mul2(tA, mul2(R, A5));   ZA = add2(ZA, tA);
                    tA = mul2(tA, mul2(B2, A3));  ZA = add2(ZA, tA);
                    tA = mul2(tA, mul2(R, A7));   ZA = add2(ZA, tA);
                    tA = mul2(tA, B8);            ZA = add2(ZA, tA);
                    tA = mul2(tA, B9);            ZA = add2(ZA, tA);

                    float t10a = ex2f(fmaf(10.0f, lr2h[0], -sbh[0]*LN10F));
                    float t10b = ex2f(fmaf(10.0f, lr2h[1], -sbh[1]*LN10F));
                    ull tB = pk2(t10a, t10b);
                    ull ZB = tB;
                    tB = mul2(tB, mul2(R, A11));  ZB = add2(ZB, tB);
                    tB = mul2(tB, mul2(B4, A3));  ZB = add2(ZB, tB);
                    tB = mul2(tB, mul2(R, A13));  ZB = add2(ZB, tB);
                    tB = mul2(tB, mul2(B2, A7));  ZB = add2(ZB, tB);
                    tB = mul2(tB, mul2(B3, A5));  ZB = add2(ZB, tB);
                    tB = mul2(tB, mul2(B8, A2));  ZB = add2(ZB, tB);
                    tB = mul2(tB, mul2(R, A17));  ZB = add2(ZB, tB);
                    tB = mul2(tB, mul2(B9, A2));  ZB = add2(ZB, tB);
                    tB = mul2(tB, mul2(R, A19));  ZB = add2(ZB, tB);

                    ull Z = add2(ZA, ZB);

                    float Z0, Z1;
                    upk2(Z0, Z1, Z);
                    #pragma unroll
                    for (int h = 0; h < 2; h++){
                        float Zh  = h ? Z1 : Z0;
                        float d   = dvp[p][h];
                        float lgfd = lut[(int)d];
                        float x = fmaf(-d, lr2h[h], lg2f(Zh));
                        srow[rr] += fmaf(sbh[h], lgfd, x);
                    }
                }
            }

            #pragma unroll
            for (int rr = 0; rr < 8; rr++){
                float s = srow[rr];
                s += __shfl_xor_sync(0xffffffffu, s, 1);
                s += __shfl_xor_sync(0xffffffffu, s, 2);
                s += __shfl_xor_sync(0xffffffffu, s, 4);
                s += __shfl_xor_sync(0xffffffffu, s, 8);
                s += __shfl_xor_sync(0xffffffffu, s, 16);
                if (lane == 0) g_part[cbc][row0 + cwid*8 + rr] = s;
            }
        }
        __syncthreads();
    }
}

// ===========================================================================
// K3: finalize — sum 8 colblock partials, scale by LN2/1024
// ===========================================================================
__global__ void k3_final(float* __restrict__ out)
{
    int row = blockIdx.x * 256 + threadIdx.x;
    float s = 0.0f;
    #pragma unroll
    for (int cb = 0; cb < 8; cb++) s += g_part[cb][row];
    out[row] = s * 6.7690154351557146e-4f;   // ln2 / 1024
}

// ===========================================================================
extern "C" void kernel_launch(void* const* d_in, const int* in_sizes, int n_in,
                              void* d_out, int out_size)
{
    const float* w    = (const float*)d_in[0];
    const float* data = (const float*)d_in[1];
    const float* W1r  = (const float*)d_in[2];
    const float* b1r  = (const float*)d_in[3];
    const float* W2r  = (const float*)d_in[4];
    const float* b2r  = (const float*)d_in[5];
    const float* W3r  = (const float*)d_in[6];
    const float* b3r  = (const float*)d_in[7];
    const float* W1v  = (const float*)d_in[8];
    const float* b1v  = (const float*)d_in[9];
    const float* W2v  = (const float*)d_in[10];
    const float* b2v  = (const float*)d_in[11];
    const float* W3v  = (const float*)d_in[12];
    const float* b3v  = (const float*)d_in[13];
    float* out = (float*)d_out;

    static bool attr_set = false;
    if (!attr_set){
        cudaFuncSetAttribute(k1_mlp12, cudaFuncAttributeMaxDynamicSharedMemorySize,
                             K1_SMEM_FLOATS * (int)sizeof(float));
        cudaFuncSetAttribute(k2_layer3, cudaFuncAttributeMaxDynamicSharedMemorySize,
                             K2_SMEM_BYTES);
        attr_set = true;
    }

    k1_mlp12<<<R_TOTAL/64, 256, K1_SMEM_FLOATS * sizeof(float)>>>(
        w, W1r, b1r, W2r, b2r, W1v, b1v, W2v, b2v);

    dim3 g2(R_TOTAL/32, 2);
    k2_layer3<<<g2, 256, K2_SMEM_BYTES>>>(
        data, W3r, b3r, W3v, b3v);

    k3_final<<<R_TOTAL/256, 256>>>(out);
}

// round 16
// speedup vs baseline: 1.4661x; 1.4661x over previous
#include <cuda_runtime.h>
#include <cuda_bf16.h>

#define R_TOTAL 65536   // T*B = 2048*32
#define XDIM    1024

// ---- scratch (static device arrays; no allocation) ----
__device__ float g_h2[(size_t)R_TOTAL * 128];   // [row][mlp(2)][64]   32 MB
__device__ float g_part[8][R_TOTAL];            // per-colblock partial row sums (log2-domain)

__device__ __forceinline__ float ex2f(float x){ float r; asm("ex2.approx.f32 %0, %1;" : "=f"(r) : "f"(x)); return r; }
__device__ __forceinline__ float lg2f(float x){ float r; asm("lg2.approx.f32 %0, %1;" : "=f"(r) : "f"(x)); return r; }

__device__ __forceinline__ float tanh_fast(float x){
    float xc = fminf(fmaxf(x, -9.0f), 9.0f);
    float e  = ex2f(xc * 2.885390081777927f);   // e^{2x}
    return __fdividef(e - 1.0f, e + 1.0f);
}

// ---- packed f32x2 helpers ----
typedef unsigned long long ull;
__device__ __forceinline__ void ffma2(ull &d, ull a, ull b){
    asm("fma.rn.f32x2 %0, %1, %2, %0;" : "+l"(d) : "l"(a), "l"(b));
}
__device__ __forceinline__ ull mul2(ull a, ull b){
    ull d; asm("mul.rn.f32x2 %0, %1, %2;" : "=l"(d) : "l"(a), "l"(b)); return d;
}
__device__ __forceinline__ ull add2(ull a, ull b){
    ull d; asm("add.rn.f32x2 %0, %1, %2;" : "=l"(d) : "l"(a), "l"(b)); return d;
}
__device__ __forceinline__ ull pk2(float lo, float hi){
    ull d; asm("mov.b64 %0, {%1, %2};" : "=l"(d) : "f"(lo), "f"(hi)); return d;
}
__device__ __forceinline__ void upk2(float &lo, float &hi, ull u){
    asm("mov.b64 {%0, %1}, %2;" : "=f"(lo), "=f"(hi) : "l"(u));
}
__device__ __forceinline__ ull dup2(float f){
    ull d; asm("mov.b64 %0, {%1, %1};" : "=l"(d) : "f"(f)); return d;
}
__device__ __forceinline__ ull pack_dup(float f){
    unsigned int b = __float_as_uint(f);
    return ((ull)b << 32) | (ull)b;
}
__device__ __forceinline__ ull pack2i(float f0, float f1){
    return ((ull)__float_as_uint(f1) << 32) | (ull)__float_as_uint(f0);
}
__device__ __forceinline__ ull ex2_2(ull g){
    float l, h; upk2(l, h, g);
    return pk2(ex2f(l), ex2f(h));
}

// ===========================================================================
// K1: layers 1+2 for both MLPs. 64 rows per block, 256 threads.
// Layer-1 accumulators split (2 partials each) for chain-depth 8 + 8 ILP chains.
// ===========================================================================
#define K1_XSH   0
#define K1_H1T   (64*32)
#define K1_W2SH  (K1_H1T + 2*256*68)
#define K1_SMEM_FLOATS (K1_W2SH + 2*64*64)

__global__ void __launch_bounds__(256, 1) k1_mlp12(
    const float* __restrict__ w,
    const float* __restrict__ W1r, const float* __restrict__ b1r,
    const float* __restrict__ W2r, const float* __restrict__ b2r,
    const float* __restrict__ W1v, const float* __restrict__ b1v,
    const float* __restrict__ W2v, const float* __restrict__ b2v)
{
    extern __shared__ float sm[];
    float* xsh  = sm + K1_XSH;
    float* h1t  = sm + K1_H1T;     // [m][k][r] stride 68
    float* w2sh = sm + K1_W2SH;

    const int tid  = threadIdx.x;
    const int row0 = blockIdx.x * 64;

    {
        const float4* src = (const float4*)(w + (size_t)row0 * 32);
        float4* dst = (float4*)xsh;
        for (int i = tid; i < 64*32/4; i += 256) dst[i] = src[i];
    }

    const int c = tid;
    float w1a[16], w1b[16];
    #pragma unroll
    for (int k = 0; k < 16; k++){ w1a[k] = W1r[k*256 + c]; w1b[k] = W1v[k*256 + c]; }
    const float ba = b1r[c], bb = b1v[c];
    __syncthreads();

    #pragma unroll 2
    for (int r2 = 0; r2 < 64; r2 += 2){
        float h0p[2], h1p[2];
        #pragma unroll
        for (int u = 0; u < 2; u++){
            const int r = r2 + u;
            float xr[32];
            #pragma unroll
            for (int q = 0; q < 8; q++) *(float4*)&xr[q*4] = *(float4*)&xsh[r*32 + q*4];
            // split accumulators: 4 independent chains per (row, mlp-pair)
            float a0 = ba, a1 = bb, e0 = 0.0f, e1 = 0.0f;
            #pragma unroll
            for (int k = 0; k < 8; k++){
                a0 = fmaf(xr[k],      w1a[k],     a0);
                e0 = fmaf(xr[k + 16], w1a[k + 8], e0);
                a1 = fmaf(xr[k + 8],  w1b[k],     a1);
                e1 = fmaf(xr[k + 24], w1b[k + 8], e1);
            }
            h0p[u] = tanh_fast(a0 + e0);
            h1p[u] = tanh_fast(a1 + e1);
        }
        *(ull*)&h1t[(0*256 + c)*68 + r2] = pack2i(h0p[0], h0p[1]);
        *(ull*)&h1t[(1*256 + c)*68 + r2] = pack2i(h1p[0], h1p[1]);
    }

    const int ci = tid & 15, rg = tid >> 4;
    const int c0 = ci * 4,  r0 = rg * 4;

    ull acc[2][2][4];
    {
        float4 br = *(const float4*)&b2r[c0];
        float4 bv = *(const float4*)&b2v[c0];
        #pragma unroll
        for (int rp = 0; rp < 2; rp++){
            acc[0][rp][0] = pack_dup(br.x); acc[0][rp][1] = pack_dup(br.y);
            acc[0][rp][2] = pack_dup(br.z); acc[0][rp][3] = pack_dup(br.w);
            acc[1][rp][0] = pack_dup(bv.x); acc[1][rp][1] = pack_dup(bv.y);
            acc[1][rp][2] = pack_dup(bv.z); acc[1][rp][3] = pack_dup(bv.w);
        }
    }

    for (int kc = 0; kc < 4; kc++){
        __syncthreads();
        for (int q = tid; q < 2048; q += 256){
            int m   = q >> 10;
            int rem = q & 1023;
            int kk  = rem >> 4;
            int cq  = rem & 15;
            const float* W2m = m ? W2v : W2r;
            *(float4*)&w2sh[(m*64 + kk)*64 + cq*4] =
                *(const float4*)&W2m[(kc*64 + kk)*64 + cq*4];
        }
        __syncthreads();
        #pragma unroll 4
        for (int kk = 0; kk < 64; kk++){
            const int k = kc*64 + kk;
            float4 wr = *(float4*)&w2sh[(0*64 + kk)*64 + c0];
            float4 wv = *(float4*)&w2sh[(1*64 + kk)*64 + c0];
            ulonglong2 hA = *(const ulonglong2*)&h1t[(0*256 + k)*68 + r0];
            ulonglong2 hB = *(const ulonglong2*)&h1t[(1*256 + k)*68 + r0];
            ull wd;
            wd = dup2(wr.x); ffma2(acc[0][0][0], hA.x, wd); ffma2(acc[0][1][0], hA.y, wd);
            wd = dup2(wr.y); ffma2(acc[0][0][1], hA.x, wd); ffma2(acc[0][1][1], hA.y, wd);
            wd = dup2(wr.z); ffma2(acc[0][0][2], hA.x, wd); ffma2(acc[0][1][2], hA.y, wd);
            wd = dup2(wr.w); ffma2(acc[0][0][3], hA.x, wd); ffma2(acc[0][1][3], hA.y, wd);
            wd = dup2(wv.x); ffma2(acc[1][0][0], hB.x, wd); ffma2(acc[1][1][0], hB.y, wd);
            wd = dup2(wv.y); ffma2(acc[1][0][1], hB.x, wd); ffma2(acc[1][1][1], hB.y, wd);
            wd = dup2(wv.z); ffma2(acc[1][0][2], hB.x, wd); ffma2(acc[1][1][2], hB.y, wd);
            wd = dup2(wv.w); ffma2(acc[1][0][3], hB.x, wd); ffma2(acc[1][1][3], hB.y, wd);
        }
    }

    #pragma unroll
    for (int m = 0; m < 2; m++){
        #pragma unroll
        for (int rp = 0; rp < 2; rp++){
            float lo0, hi0, lo1, hi1, lo2, hi2, lo3, hi3;
            upk2(lo0, hi0, acc[m][rp][0]);
            upk2(lo1, hi1, acc[m][rp][1]);
            upk2(lo2, hi2, acc[m][rp][2]);
            upk2(lo3, hi3, acc[m][rp][3]);
            float4 oLo, oHi;
            oLo.x = tanh_fast(lo0); oLo.y = tanh_fast(lo1);
            oLo.z = tanh_fast(lo2); oLo.w = tanh_fast(lo3);
            oHi.x = tanh_fast(hi0); oHi.y = tanh_fast(hi1);
            oHi.z = tanh_fast(hi2); oHi.w = tanh_fast(hi3);
            const int rowLo = row0 + r0 + rp*2;
            *(float4*)&g_h2[((size_t)rowLo*2 + m)*64 + c0]     = oLo;
            *(float4*)&g_h2[((size_t)(rowLo+1)*2 + m)*64 + c0] = oHi;
        }
    }
}

// ===========================================================================
// K2: fused layer 3 + decode + split-chain prime-factored Z + reduction.
// 3 CTAs/SM. Block = 128 threads, 32 rows x 128 cols, grid (2048, 8). (R12)
// ===========================================================================
#define K2_OFF_W3   (32*128*8)                 // 32768
#define K2_OFF_LUT  (K2_OFF_W3 + 2*32*128*4)   // 65536
#define K2_SMEM_BYTES (K2_OFF_LUT + 64)        // 65600

__global__ void __launch_bounds__(128, 3) k2_layer3(
    const float* __restrict__ data,
    const float* __restrict__ W3r, const float* __restrict__ b3r,
    const float* __restrict__ W3v, const float* __restrict__ b3v)
{
    extern __shared__ __align__(16) char smraw[];
    ull*   h2p  = (ull*)smraw;                       // 4096 ull
    float* w3sh = (float*)(smraw + K2_OFF_W3);       // 8192 floats ([m][kk<32][128])
    float* lut  = (float*)(smraw + K2_OFF_LUT);      // 10 floats: ln(d!)

    const int tid  = threadIdx.x;
    const int row0 = blockIdx.x * 32;
    const int cb   = blockIdx.y;          // colblock (128 cols each)
    const int wid  = tid >> 5;
    const int lane = tid & 31;

    if (tid < 10){
        const float LGF[10] = {
            0.0f, 0.0f, 0.6931471805599453f, 1.791759469228055f, 3.1780538303479458f,
            4.787491742782046f, 6.579251212010101f, 8.525161361065415f,
            10.604602902745251f, 12.801827480081469f };
        lut[tid] = LGF[tid];
    }

    // stage h2 as duplicated (h,h) pairs: h2p[rowLocal*128 + m*64 + k]
    for (int q = tid; q < 4096; q += 128){
        int rr  = q >> 7;
        int rem = q & 127;
        h2p[rr*128 + rem] = pack_dup(g_h2[(size_t)(row0 + rr)*128 + rem]);
    }

    // accumulators: acc[m][rr(8)][p(2)]
    ull acc[2][8][2];
    {
        const float4* br4 = (const float4*)b3r;
        const float4* bv4 = (const float4*)b3v;
        float4 br = br4[cb*32 + lane];
        float4 bv = bv4[cb*32 + lane];
        #pragma unroll
        for (int rr = 0; rr < 8; rr++){
            acc[0][rr][0] = pack2i(br.x, br.y);
            acc[0][rr][1] = pack2i(br.z, br.w);
            acc[1][rr][0] = pack2i(bv.x, bv.y);
            acc[1][rr][1] = pack2i(bv.z, bv.w);
        }
    }

    // GEMM over K=64 in two k-halves of 32 (W3 tile restaged between halves)
    const ulonglong2* w3u = (const ulonglong2*)w3sh;    // [(m*32+kk)*32 + lane]
    const ull* h2row = h2p + wid*8*128;
    const float4* s0 = (const float4*)W3r;
    const float4* s1 = (const float4*)W3v;

    #pragma unroll
    for (int kh = 0; kh < 2; kh++){
        __syncthreads();   // kh=0: h2p/lut visible; kh=1: previous w3 half consumed
        {
            float4* dst = (float4*)w3sh;
            for (int q = tid; q < 2048; q += 128){
                int m  = q >> 10;
                int kk = (q >> 5) & 31;
                int cf = q & 31;
                dst[q] = (m ? s1 : s0)[(kh*32 + kk)*256 + cb*32 + cf];
            }
        }
        __syncthreads();

        #pragma unroll 4
        for (int k = 0; k < 32; k += 2){
            ulonglong2 wr0 = w3u[(size_t)k*32 + lane];
            ulonglong2 wr1 = w3u[(size_t)(k+1)*32 + lane];
            ulonglong2 wv0 = w3u[(size_t)(32 + k)*32 + lane];
            ulonglong2 wv1 = w3u[(size_t)(32 + k + 1)*32 + lane];
            const int kg = kh*32 + k;
            #pragma unroll
            for (int rr = 0; rr < 8; rr++){
                ulonglong2 h0p = *(const ulonglong2*)&h2row[rr*128 + kg];
                ulonglong2 h1p = *(const ulonglong2*)&h2row[rr*128 + 64 + kg];
                ffma2(acc[0][rr][0], h0p.x, wr0.x);
                ffma2(acc[0][rr][1], h0p.x, wr0.y);
                ffma2(acc[0][rr][0], h0p.y, wr1.x);
                ffma2(acc[0][rr][1], h0p.y, wr1.y);
                ffma2(acc[1][rr][0], h1p.x, wv0.x);
                ffma2(acc[1][rr][1], h1p.x, wv0.y);
                ffma2(acc[1][rr][0], h1p.y, wv1.x);
                ffma2(acc[1][rr][1], h1p.y, wv1.y);
            }
        }
    }

    // ---- fused elementwise (log2-domain; final LN2 scale in K3) ----
    const float LOG2E = 1.4426950408889634f;
    const float C_NLG2LN2 = 0.5287663729448977f;   // -log2(ln 2)
    const ull   ONE2 = 0x3F8000003F800000ULL;
    const float LN10F = 15.104412573075516f;       // ln(10!)
    const ull CN2  = pack_dup(-0.6931471805599453f);
    const ull CN3  = pack_dup(-1.0986122886681098f);
    const ull CN5  = pack_dup(-1.6094379124341003f);
    const ull CN7  = pack_dup(-1.9459101090932196f);
    const ull CN11 = pack_dup(-2.3978952727983707f);
    const ull CN13 = pack_dup(-2.5649493574615367f);
    const ull CN17 = pack_dup(-2.833213344056216f);
    const ull CN19 = pack_dup(-2.9444389791664403f);

    float srow[8];
    #pragma unroll
    for (int rr = 0; rr < 8; rr++) srow[rr] = 0.0f;

    #pragma unroll
    for (int rr = 0; rr < 8; rr++){
        const int rowg = row0 + wid*8 + rr;
        float4 d4 = *(const float4*)&data[(size_t)rowg*1024 + cb*128 + lane*4];
        float dvp[2][2] = {{d4.x, d4.y}, {d4.z, d4.w}};

        #pragma unroll
        for (int p = 0; p < 2; p++){
            float ya0, ya1, yb0, yb1;
            upk2(ya0, ya1, acc[0][rr][p]);
            upk2(yb0, yb1, acc[1][rr][p]);

            float lr2h[2], sbh[2], rateh[2];
            #pragma unroll
            for (int h = 0; h < 2; h++){
                float ya = h ? ya1 : ya0;
                float yb = h ? yb1 : yb0;
                float ta  = ya * LOG2E;
                float spa = fmaxf(ta, 0.0f) + lg2f(1.0f + ex2f(-fabsf(ta)));
                lr2h[h]   = C_NLG2LN2 - lg2f(spa);            // log2(rate)
                float tb  = yb * LOG2E;
                sbh[h]    = fmaxf(tb, 0.0f) + lg2f(1.0f + ex2f(-fabsf(tb)));  // v/ln2
                rateh[h]  = ex2f(lr2h[h]);
            }

            ull sb2 = pk2(sbh[0], sbh[1]);
            ull A2  = ex2_2(mul2(sb2, CN2));
            ull A3  = ex2_2(mul2(sb2, CN3));
            ull A5  = ex2_2(mul2(sb2, CN5));
            ull A7  = ex2_2(mul2(sb2, CN7));
            ull A11 = ex2_2(mul2(sb2, CN11));
            ull A13 = ex2_2(mul2(sb2, CN13));
            ull A17 = ex2_2(mul2(sb2, CN17));
            ull A19 = ex2_2(mul2(sb2, CN19));

            ull R = pk2(rateh[0], rateh[1]);

            ull B2 = mul2(R, A2);
            ull B3 = mul2(R, A3);
            ull B4 = mul2(B2, A2);
            ull B8 = mul2(B4, A2);
            ull B9 = mul2(B3, A3);

            // chain A: j = 1..9
            ull tA = R;
            ull ZA = add2(ONE2, tA);
            tA = mul2(tA, B2);            ZA = add2(ZA, tA);
            tA = mul2(tA, B3);            ZA = add2(ZA, tA);
            tA = mul2(tA, B4);            ZA = add2(ZA, tA);
            tA = mul2(tA, mul2(R, A5));   ZA = add2(ZA, tA);
            tA = mul2(tA, mul2(B2, A3));  ZA = add2(ZA, tA);
            tA = mul2(tA, mul2(R, A7));   ZA = add2(ZA, tA);
            tA = mul2(tA, B8);            ZA = add2(ZA, tA);
            tA = mul2(tA, B9);            ZA = add2(ZA, tA);

            // chain B: t10 directly, then j = 11..19
            float t10a = ex2f(fmaf(10.0f, lr2h[0], -sbh[0]*LN10F));
            float t10b = ex2f(fmaf(10.0f, lr2h[1], -sbh[1]*LN10F));
            ull tB = pk2(t10a, t10b);
            ull ZB = tB;
            tB = mul2(tB, mul2(R, A11));  ZB = add2(ZB, tB);
            tB = mul2(tB, mul2(B4, A3));  ZB = add2(ZB, tB);   // B12
            tB = mul2(tB, mul2(R, A13));  ZB = add2(ZB, tB);
            tB = mul2(tB, mul2(B2, A7));  ZB = add2(ZB, tB);   // B14
            tB = mul2(tB, mul2(B3, A5));  ZB = add2(ZB, tB);   // B15
            tB = mul2(tB, mul2(B8, A2));  ZB = add2(ZB, tB);   // B16
            tB = mul2(tB, mul2(R, A17));  ZB = add2(ZB, tB);
            tB = mul2(tB, mul2(B9, A2));  ZB = add2(ZB, tB);   // B18
            tB = mul2(tB, mul2(R, A19));  ZB = add2(ZB, tB);

            ull Z = add2(ZA, ZB);

            float Z0, Z1;
            upk2(Z0, Z1, Z);
            #pragma unroll
            for (int h = 0; h < 2; h++){
                float Zh  = h ? Z1 : Z0;
                float d   = dvp[p][h];
                float lgfd = lut[(int)d];
                float x = fmaf(-d, lr2h[h], lg2f(Zh));
                srow[rr] += fmaf(sbh[h], lgfd, x);
            }
        }
    }

    // reduce row-partials across the warp's 32 lanes
    #pragma unroll
    for (int rr = 0; rr < 8; rr++){
        float s = srow[rr];
        s += __shfl_xor_sync(0xffffffffu, s, 1);
        s += __shfl_xor_sync(0xffffffffu, s, 2);
        s += __shfl_xor_sync(0xffffffffu, s, 4);
        s += __shfl_xor_sync(0xffffffffu, s, 8);
        s += __shfl_xor_sync(0xffffffffu, s, 16);
        srow[rr] = s;
    }
    if (lane == 0){
        #pragma unroll
        for (int rr = 0; rr < 8; rr++)
            g_part[cb][row0 + wid*8 + rr] = srow[rr];
    }
}

// ===========================================================================
// K3: finalize — sum 8 colblock partials, scale by LN2/1024
// ===========================================================================
__global__ void k3_final(float* __restrict__ out)
{
    int row = blockIdx.x * 256 + threadIdx.x;
    float s = 0.0f;
    #pragma unroll
    for (int cb = 0; cb < 8; cb++) s += g_part[cb][row];
    out[row] = s * 6.7690154351557146e-4f;   // ln2 / 1024
}

// ===========================================================================
extern "C" void kernel_launch(void* const* d_in, const int* in_sizes, int n_in,
                              void* d_out, int out_size)
{
    const float* w    = (const float*)d_in[0];
    const float* data = (const float*)d_in[1];
    const float* W1r  = (const float*)d_in[2];
    const float* b1r  = (const float*)d_in[3];
    const float* W2r  = (const float*)d_in[4];
    const float* b2r  = (const float*)d_in[5];
    const float* W3r  = (const float*)d_in[6];
    const float* b3r  = (const float*)d_in[7];
    const float* W1v  = (const float*)d_in[8];
    const float* b1v  = (const float*)d_in[9];
    const float* W2v  = (const float*)d_in[10];
    const float* b2v  = (const float*)d_in[11];
    const float* W3v  = (const float*)d_in[12];
    const float* b3v  = (const float*)d_in[13];
    float* out = (float*)d_out;

    static bool attr_set = false;
    if (!attr_set){
        cudaFuncSetAttribute(k1_mlp12, cudaFuncAttributeMaxDynamicSharedMemorySize,
                             K1_SMEM_FLOATS * (int)sizeof(float));
        cudaFuncSetAttribute(k2_layer3, cudaFuncAttributeMaxDynamicSharedMemorySize,
                             K2_SMEM_BYTES);
        attr_set = true;
    }

    k1_mlp12<<<R_TOTAL/64, 256, K1_SMEM_FLOATS * sizeof(float)>>>(
        w, W1r, b1r, W2r, b2r, W1v, b1v, W2v, b2v);

    dim3 g2(R_TOTAL/32, 8);
    k2_layer3<<<g2, 128, K2_SMEM_BYTES>>>(
        data, W3r, b3r, W3v, b3v);

    k3_final<<<R_TOTAL/256, 256>>>(out);
}